// round 14
// baseline (speedup 1.0000x reference)
#include <cuda_runtime.h>

// SmartDoorClassifierv1 — fused CNN (LIF collapses: alpha = exp(-200) == 0 in fp32).
// Round 13: 4 CTAs/SM attempt with both constraints engineered:
//  - regs<=64: stage-2 e-split (acc 16 + patch 18); P1_RS=36 keeps float4
//    patch rows legal for BOTH e parities (row offsets always 16B-aligned).
//  - smem<=56.7KB: halo-sharing (plane c bottom zero row == plane c+1 top zero
//    row) shrinks p1p/p2p plane strides to 1188/306.
// Keeps R12's vectorized bank-padded weights and stage-1 form.

#define THREADS 256

// dynamic smem layout (float indices)
//  p1p  : 7*1188 + 1224 = 9540  (8 planes, stride 1188, shared zero halos, row stride 36)
//  p2p  : 7*306  + 324  = 2466  (8 planes, stride 306, shared zero halos, row stride 18)
//  p3   : 512
//  sw1  : 64
//  sw2p : 772   (2 ocg blocks, stride 388; per-(o,ic) stride 12)
//  sw3p : 796   (oc stride 100, per-ic stride 12)
//  red  : 16
#define OFF_P1   0
#define OFF_P2   9540
#define OFF_P3   12008
#define OFF_W1   12520
#define OFF_W2   12584
#define OFF_W3   13356
#define OFF_RED  14152
#define SMEM_FLOATS (OFF_RED + 16)   // 14168 floats = 56672 B

#define P1_RS   36
#define P1_PL   1188      // 33 rows * 36 (halo-shared)
#define P2_RS   18
#define P2_PL   306       // 17 rows * 18 (halo-shared)

__global__ __launch_bounds__(THREADS, 4)
void snn_fused_kernel(const float* __restrict__ x,
                      const float* __restrict__ w1,
                      const float* __restrict__ w2,
                      const float* __restrict__ w3,
                      const float* __restrict__ wfc,
                      float* __restrict__ out)
{
    extern __shared__ float smem[];
    float* p1p  = smem + OFF_P1;
    float* p2p  = smem + OFF_P2;
    float* p3   = smem + OFF_P3;
    float* sw1  = smem + OFF_W1;
    float* sw2p = smem + OFF_W2;
    float* sw3p = smem + OFF_W3;
    float* red  = smem + OFF_RED;

    const int tid = threadIdx.x;
    const int n   = blockIdx.x;

    // ---- init: weights (padded layouts) + shared-halo zero fill ----
    if (tid < 64) sw1[tid] = w1[tid];
    for (int i = tid; i < 576; i += THREADS) {
        int oc = i / 72, rem = i % 72, ic = rem / 9, k = rem % 9;
        sw2p[(oc >> 2) * 388 + ((oc & 3) * 8 + ic) * 12 + k] = w2[i];
        sw3p[oc * 100 + ic * 12 + k] = w3[i];
    }
    // p1p: 9 boundary rows (k*1188, cols 0..33) + side cols per plane
    for (int i = tid; i < 9 * 34; i += THREADS) {
        int b = i / 34, c = i % 34;
        p1p[b * P1_PL + c] = 0.f;
    }
    for (int i = tid; i < 8 * 32; i += THREADS) {
        int ic = i / 32, r = (i % 32) + 1;
        p1p[ic * P1_PL + r * P1_RS] = 0.f;
        p1p[ic * P1_PL + r * P1_RS + 33] = 0.f;
    }
    // p2p: 9 boundary rows (k*306, cols 0..17) + side cols per plane
    for (int i = tid; i < 9 * 18; i += THREADS) {
        int b = i / 18, c = i % 18;
        p2p[b * P2_PL + c] = 0.f;
    }
    for (int i = tid; i < 8 * 16; i += THREADS) {
        int ic = i / 16, r = (i % 16) + 1;
        p2p[ic * P2_PL + r * P2_RS] = 0.f;
        p2p[ic * P2_PL + r * P2_RS + 17] = 0.f;
    }
    __syncthreads();

    // ================= Stage 1: conv1(2x2,s2) + floor(relu) + pool2 =========
    const float* xb = x + (size_t)n * (2 * 128 * 128);
    #pragma unroll 1
    for (int it = 0; it < 4; it++) {
        int pos = tid + it * THREADS;          // 0..1023
        int py = pos >> 5, px = pos & 31;
        const float* src0 = xb + (4 * py) * 128 + 4 * px;   // ch0
        const float* src1 = src0 + 16384;                   // ch1
        float4 c0r0 = *reinterpret_cast<const float4*>(src0);
        float4 c0r1 = *reinterpret_cast<const float4*>(src0 + 128);
        float4 c0r2 = *reinterpret_cast<const float4*>(src0 + 256);
        float4 c0r3 = *reinterpret_cast<const float4*>(src0 + 384);
        float4 c1r0 = *reinterpret_cast<const float4*>(src1);
        float4 c1r1 = *reinterpret_cast<const float4*>(src1 + 128);
        float4 c1r2 = *reinterpret_cast<const float4*>(src1 + 256);
        float4 c1r3 = *reinterpret_cast<const float4*>(src1 + 384);

        float* dst = p1p + (py + 1) * P1_RS + (px + 1);
        #pragma unroll
        for (int oc = 0; oc < 8; oc++) {
            const float* wb = sw1 + oc * 8;
            float4 wA = *reinterpret_cast<const float4*>(wb);      // ch0 2x2
            float4 wB = *reinterpret_cast<const float4*>(wb + 4);  // ch1 2x2
            float v00, v01, v10, v11;
            v00 = c0r0.x * wA.x;               v01 = c0r0.z * wA.x;
            v00 = fmaf(c0r0.y, wA.y, v00);     v01 = fmaf(c0r0.w, wA.y, v01);
            v00 = fmaf(c0r1.x, wA.z, v00);     v01 = fmaf(c0r1.z, wA.z, v01);
            v00 = fmaf(c0r1.y, wA.w, v00);     v01 = fmaf(c0r1.w, wA.w, v01);
            v00 = fmaf(c1r0.x, wB.x, v00);     v01 = fmaf(c1r0.z, wB.x, v01);
            v00 = fmaf(c1r0.y, wB.y, v00);     v01 = fmaf(c1r0.w, wB.y, v01);
            v00 = fmaf(c1r1.x, wB.z, v00);     v01 = fmaf(c1r1.z, wB.z, v01);
            v00 = fmaf(c1r1.y, wB.w, v00);     v01 = fmaf(c1r1.w, wB.w, v01);

            v10 = c0r2.x * wA.x;               v11 = c0r2.z * wA.x;
            v10 = fmaf(c0r2.y, wA.y, v10);     v11 = fmaf(c0r2.w, wA.y, v11);
            v10 = fmaf(c0r3.x, wA.z, v10);     v11 = fmaf(c0r3.z, wA.z, v11);
            v10 = fmaf(c0r3.y, wA.w, v10);     v11 = fmaf(c0r3.w, wA.w, v11);
            v10 = fmaf(c1r2.x, wB.x, v10);     v11 = fmaf(c1r2.z, wB.x, v11);
            v10 = fmaf(c1r2.y, wB.y, v10);     v11 = fmaf(c1r2.w, wB.y, v11);
            v10 = fmaf(c1r3.x, wB.z, v10);     v11 = fmaf(c1r3.z, wB.z, v11);
            v10 = fmaf(c1r3.y, wB.w, v10);     v11 = fmaf(c1r3.w, wB.w, v11);

            float m = fmaxf(fmaxf(floorf(fmaxf(v00, 0.f)),
                                  floorf(fmaxf(v01, 0.f))),
                            fmaxf(floorf(fmaxf(v10, 0.f)),
                                  floorf(fmaxf(v11, 0.f))));
            dst[oc * P1_PL] = m;
        }
    }
    __syncthreads();

    // ================= Stage 2: conv2(3x3,p1) + floor(relu) + pool2 =========
    // Thread = 4 oc x 2 adjacent pooled positions, split over output rows e.
    // Per pass: acc[4][2][2] (16) + patch[3][6] (18). All patch rows are
    // 16B-aligned (stride 36), so float4+float2 for both e parities.
    {
        int pp  = tid >> 1;          // 0..127 position pair
        int ocg = tid & 1;           // oc base = ocg*4
        int py  = pp >> 3;           // 0..15
        int pxp = pp & 7;            // pooled px = 2*pxp + p

        float m[4][2];
        #pragma unroll
        for (int o = 0; o < 4; o++) { m[o][0] = 0.f; m[o][1] = 0.f; }

        #pragma unroll 1
        for (int e = 0; e < 2; e++) {
            float acc[4][2][2];      // [o][p][dx]
            #pragma unroll
            for (int o = 0; o < 4; o++)
                #pragma unroll
                for (int p = 0; p < 2; p++) {
                    acc[o][p][0] = 0.f; acc[o][p][1] = 0.f;
                }

            #pragma unroll 1
            for (int ic = 0; ic < 8; ic++) {
                const float* base = p1p + ic * P1_PL + (2 * py + e) * P1_RS
                                  + 4 * pxp;
                float patch[3][6];
                #pragma unroll
                for (int r = 0; r < 3; r++) {
                    float4 a = *reinterpret_cast<const float4*>(base + r * P1_RS);
                    float2 c = *reinterpret_cast<const float2*>(base + r * P1_RS + 4);
                    patch[r][0] = a.x; patch[r][1] = a.y;
                    patch[r][2] = a.z; patch[r][3] = a.w;
                    patch[r][4] = c.x; patch[r][5] = c.y;
                }
                const float* wblk = sw2p + ocg * 388 + ic * 12;
                #pragma unroll
                for (int o = 0; o < 4; o++) {
                    const float* wb = wblk + o * 96;
                    float4 wA = *reinterpret_cast<const float4*>(wb);
                    float4 wB = *reinterpret_cast<const float4*>(wb + 4);
                    float wk[9] = {wA.x, wA.y, wA.z, wA.w,
                                   wB.x, wB.y, wB.z, wB.w, wb[8]};
                    #pragma unroll
                    for (int p = 0; p < 2; p++) {
                        #pragma unroll
                        for (int d = 0; d < 2; d++) {
                            float a = acc[o][p][d];
                            #pragma unroll
                            for (int ky = 0; ky < 3; ky++)
                                #pragma unroll
                                for (int kx = 0; kx < 3; kx++)
                                    a = fmaf(patch[ky][2*p + d + kx],
                                             wk[ky * 3 + kx], a);
                            acc[o][p][d] = a;
                        }
                    }
                }
            }
            #pragma unroll
            for (int o = 0; o < 4; o++)
                #pragma unroll
                for (int p = 0; p < 2; p++) {
                    float v = fmaxf(floorf(fmaxf(acc[o][p][0], 0.f)),
                                    floorf(fmaxf(acc[o][p][1], 0.f)));
                    m[o][p] = fmaxf(m[o][p], v);
                }
        }
        #pragma unroll
        for (int o = 0; o < 4; o++)
            #pragma unroll
            for (int p = 0; p < 2; p++)
                p2p[(ocg * 4 + o) * P2_PL + (py + 1) * P2_RS + (2 * pxp + p + 1)]
                    = m[o][p];
    }
    __syncthreads();

    // ================= Stage 3: conv3(3x3,p2) + floor(relu) + pool2 =========
    // 64 pooled positions; 4 threads/pos, 2 out-channels each.
    {
        int pos = tid >> 2;                // 0..63
        int ocg = tid & 3;
        int py = pos >> 3, px = pos & 7;
        float acc[2][2][2];
        #pragma unroll
        for (int j = 0; j < 2; j++)
            #pragma unroll
            for (int a = 0; a < 2; a++)
                #pragma unroll
                for (int b = 0; b < 2; b++) acc[j][a][b] = 0.f;

        #pragma unroll 1
        for (int ic = 0; ic < 8; ic++) {
            const float* base = p2p + ic * P2_PL + (2 * py) * P2_RS + 2 * px;
            float patch[4][4];
            #pragma unroll
            for (int r = 0; r < 4; r++) {
                float2 a = *reinterpret_cast<const float2*>(base + r * P2_RS);
                float2 b = *reinterpret_cast<const float2*>(base + r * P2_RS + 2);
                patch[r][0] = a.x; patch[r][1] = a.y;
                patch[r][2] = b.x; patch[r][3] = b.y;
            }
            #pragma unroll
            for (int j = 0; j < 2; j++) {
                const float* wb = sw3p + (ocg * 2 + j) * 100 + ic * 12;
                float4 wA = *reinterpret_cast<const float4*>(wb);
                float4 wB = *reinterpret_cast<const float4*>(wb + 4);
                float wk[9] = {wA.x, wA.y, wA.z, wA.w,
                               wB.x, wB.y, wB.z, wB.w, wb[8]};
                #pragma unroll
                for (int dy = 0; dy < 2; dy++) {
                    #pragma unroll
                    for (int dx = 0; dx < 2; dx++) {
                        float a = acc[j][dy][dx];
                        #pragma unroll
                        for (int ky = 0; ky < 3; ky++)
                            #pragma unroll
                            for (int kx = 0; kx < 3; kx++)
                                a = fmaf(patch[dy+ky][dx+kx], wk[ky*3+kx], a);
                        acc[j][dy][dx] = a;
                    }
                }
            }
        }
        #pragma unroll
        for (int j = 0; j < 2; j++) {
            int oc = ocg * 2 + j;
            float m = 0.f;
            #pragma unroll
            for (int dy = 0; dy < 2; dy++)
                #pragma unroll
                for (int dx = 0; dx < 2; dx++)
                    m = fmaxf(m, floorf(fmaxf(acc[j][dy][dx], 0.f)));
            p3[oc * 64 + py * 8 + px] = m;     // flatten order c*64 + y*8 + x
        }
    }
    __syncthreads();

    // ================= Stage 4: fc (512 -> 2) ===============================
    {
        float a0 = 0.f, a1 = 0.f;
        #pragma unroll
        for (int k = 0; k < 2; k++) {
            int j = tid + k * THREADS;         // 0..511
            float v = p3[j];
            a0 = fmaf(v, wfc[j],       a0);
            a1 = fmaf(v, wfc[512 + j], a1);
        }
        #pragma unroll
        for (int off = 16; off > 0; off >>= 1) {
            a0 += __shfl_down_sync(0xffffffffu, a0, off);
            a1 += __shfl_down_sync(0xffffffffu, a1, off);
        }
        if ((tid & 31) == 0) {
            red[tid >> 5]       = a0;
            red[8 + (tid >> 5)] = a1;
        }
        __syncthreads();
        if (tid == 0) {
            float s0 = 0.f, s1 = 0.f;
            #pragma unroll
            for (int i = 0; i < 8; i++) { s0 += red[i]; s1 += red[8 + i]; }
            out[n * 2 + 0] = s0;
            out[n * 2 + 1] = s1;
        }
    }
}

extern "C" void kernel_launch(void* const* d_in, const int* in_sizes, int n_in,
                              void* d_out, int out_size)
{
    const float* x   = (const float*)d_in[0];
    const float* w1  = (const float*)d_in[1];
    const float* w2  = (const float*)d_in[2];
    const float* w3  = (const float*)d_in[3];
    const float* wfc = (const float*)d_in[4];
    int nsamples = in_sizes[0] / (2 * 128 * 128);   // 1024

    size_t smem_bytes = SMEM_FLOATS * sizeof(float);  // 56672 B (~55.3 KB)
    cudaFuncSetAttribute(snn_fused_kernel,
                         cudaFuncAttributeMaxDynamicSharedMemorySize,
                         (int)smem_bytes);
    snn_fused_kernel<<<nsamples, THREADS, smem_bytes>>>(x, w1, w2, w3, wfc,
                                                        (float*)d_out);
}